// round 4
// baseline (speedup 1.0000x reference)
#include <cuda_runtime.h>
#include <cstdint>

// Problem constants
#define NROWS   131072
#define DDIM    256
#define NW      256     // codewords
#define NB      8       // books
#define LW      32      // dims per book
#define TAUQ    5.0f

#define Z_ELEMS   (NROWS * DDIM)          // 33554432
#define IDX_ELEMS (NROWS * NB)            // 1048576
#define C_ELEMS   (NW * DDIM)             // 65536

#define KEY_MARGIN 1e-3f                  // packed-vs-exact key bound is ~1e-6

// ---------- packed f32x2 helpers ----------
__device__ __forceinline__ unsigned long long pack2(float lo, float hi) {
    unsigned long long r;
    asm("mov.b64 %0, {%1, %2};" : "=l"(r) : "r"(__float_as_uint(lo)), "r"(__float_as_uint(hi)));
    return r;
}
__device__ __forceinline__ void unpack2(unsigned long long v, float& lo, float& hi) {
    unsigned a, b;
    asm("mov.b64 {%0, %1}, %2;" : "=r"(a), "=r"(b) : "l"(v));
    lo = __uint_as_float(a); hi = __uint_as_float(b);
}
__device__ __forceinline__ unsigned long long fma2(unsigned long long a, unsigned long long b, unsigned long long c) {
    unsigned long long d;
    asm("fma.rn.f32x2 %0, %1, %2, %3;" : "=l"(d) : "l"(a), "l"(b), "l"(c));
    return d;
}
__device__ __forceinline__ unsigned long long lds64(unsigned addr) {
    unsigned long long v;
    asm volatile("ld.shared.b64 %0, [%1];" : "=l"(v) : "r"(addr));
    return v;
}

// Butterfly-tree sum of 32 separately-rounded squares: replicates an XLA
// warp-shuffle row reduction (strides 16,8,4,2,1; pure mul then tree adds,
// no FMA contraction).
__device__ __forceinline__ float tree_sumsq32(const float* v) {
    float s[32];
    #pragma unroll
    for (int i = 0; i < 32; ++i) s[i] = __fmul_rn(v[i], v[i]);
    #pragma unroll
    for (int stride = 16; stride >= 1; stride >>= 1) {
        #pragma unroll
        for (int i = 0; i < stride; ++i) s[i] = __fadd_rn(s[i], s[i + stride]);
    }
    return s[0];
}

// Main kernel: one CTA = 256 rows x 1 book. Each thread owns one (row, book).
__global__ __launch_bounds__(256, 2)
void softpq_kernel(const float* __restrict__ x, const float* __restrict__ C,
                   float* __restrict__ out)
{
    __shared__ float sC[NW * LW];   // codebook slice for this book [256][32]
    __shared__ float sc2[NW];       // c2 via butterfly-tree chain

    const int tid  = threadIdx.x;
    const int book = blockIdx.y;
    const int n    = blockIdx.x * 256 + tid;

    // Load Cr slice (thread tid -> codeword tid), c2 via tree reduction.
    {
        const float4* src = reinterpret_cast<const float4*>(C);
        float4* dst = reinterpret_cast<float4*>(sC);
        float cv[32];
        #pragma unroll
        for (int j = 0; j < 8; ++j) {
            float4 v = src[tid * (DDIM/4) + book * (LW/4) + j];
            cv[4*j+0] = v.x; cv[4*j+1] = v.y; cv[4*j+2] = v.z; cv[4*j+3] = v.w;
            dst[tid * (LW/4) + j] = v;
        }
        sc2[tid] = tree_sumsq32(cv);
    }
    __syncthreads();

    // Load this thread's x sub-vector; x2 via the same tree chain.
    unsigned long long xr2[16];
    float xv[32];
    {
        const float4* xs = reinterpret_cast<const float4*>(x);
        #pragma unroll
        for (int j = 0; j < 8; ++j) {
            float4 v = xs[(size_t)n * (DDIM/4) + book * (LW/4) + j];
            xv[4*j+0] = v.x; xv[4*j+1] = v.y; xv[4*j+2] = v.z; xv[4*j+3] = v.w;
            xr2[2*j]   = pack2(v.x, v.y);
            xr2[2*j+1] = pack2(v.z, v.w);
        }
    }
    const float X2 = tree_sumsq32(xv);
    const float kshift = TAUQ * X2;   // exponent shift for stable single-pass exp

    unsigned long long z2[16];
    const unsigned long long zero64 = pack2(0.f, 0.f);
    #pragma unroll
    for (int k = 0; k < 16; ++k) z2[k] = zero64;

    float ssum = 0.f;
    float bestKey = -3.4e38f;   // exact-chain key of current best
    int   best = 0;

    const unsigned sbase = (unsigned)__cvta_generic_to_shared(sC);

    #pragma unroll 1
    for (int w = 0; w < NW; ++w) {
        unsigned a = sbase + (unsigned)(w * (LW * 4));
        unsigned long long cr[16];
        #pragma unroll
        for (int k = 0; k < 16; ++k) cr[k] = lds64(a + k * 8);

        // Fast packed dot for the softmax/Z path
        unsigned long long acc = zero64;
        #pragma unroll
        for (int k = 0; k < 16; ++k) acc = fma2(xr2[k], cr[k], acc);
        float dlo, dhi; unpack2(acc, dlo, dhi);
        float dotA = dlo + dhi;

        float tA = X2 + sc2[w];
        float keyA = -TAUQ * fmaf(-2.0f, dotA, tA);   // approx key (~1e-6 of ref-chain)

        // Candidate? Recompute the key with the reference's rounding chain:
        // ascending-k single-accumulator FFMA dot (cuBLAS SGEMM order).
        if (keyA > bestKey - KEY_MARGIN) {
            float de = 0.f;
            #pragma unroll
            for (int k = 0; k < 16; ++k) {
                float x0, x1, c0, c1;
                unpack2(xr2[k], x0, x1);
                unpack2(cr[k],  c0, c1);
                de = __fmaf_rn(x0, c0, de);
                de = __fmaf_rn(x1, c1, de);
            }
            float t    = __fadd_rn(X2, sc2[w]);        // fl(x2 + c2)
            float dist = __fmaf_rn(-2.0f, de, t);      // fl(t - 2*dot), single rounding
            float key  = __fmul_rn(-TAUQ, dist);       // fl(-5*dist)
            if (key > bestKey) { bestKey = key; best = w; }  // first-index tie-break
        }

        // Softmax/Z accumulation (tolerance 1e-3 on Z; packed path is plenty)
        float p = __expf(keyA + kshift);
        ssum += p;
        unsigned long long p2 = pack2(p, p);
        #pragma unroll
        for (int k = 0; k < 16; ++k) z2[k] = fma2(p2, cr[k], z2[k]);
    }

    const float invs = 1.0f / ssum;

    // Write Z (float4 stores)
    {
        float4* zo = reinterpret_cast<float4*>(out);
        #pragma unroll
        for (int j = 0; j < 8; ++j) {
            float a0, a1, a2, a3;
            unpack2(z2[2*j],   a0, a1);
            unpack2(z2[2*j+1], a2, a3);
            float4 v = make_float4(a0 * invs, a1 * invs, a2 * invs, a3 * invs);
            zo[(size_t)n * (DDIM/4) + book * (LW/4) + j] = v;
        }
    }

    // Write idx (as float, numeric cast)
    out[(size_t)Z_ELEMS + (size_t)n * NB + book] = (float)best;
}

// Copy C to tail of output
__global__ void copy_c_kernel(const float* __restrict__ C, float* __restrict__ out)
{
    int i = blockIdx.x * blockDim.x + threadIdx.x;
    if (i < C_ELEMS) out[(size_t)Z_ELEMS + IDX_ELEMS + i] = C[i];
}

extern "C" void kernel_launch(void* const* d_in, const int* in_sizes, int n_in,
                              void* d_out, int out_size)
{
    const float* x = (const float*)d_in[0];
    const float* C = (const float*)d_in[1];
    float* out = (float*)d_out;

    dim3 grid(NROWS / 256, NB);
    softpq_kernel<<<grid, 256>>>(x, C, out);
    copy_c_kernel<<<(C_ELEMS + 255) / 256, 256>>>(C, out);
}